// round 17
// baseline (speedup 1.0000x reference)
#include <cuda_runtime.h>
#include <stdint.h>

// BurgerDissipativeLossOperator — init-free formulation (R16) + k_final MLP.
//
//   du[i]  = (u1[i]*A[i] - B[i]) / max(cnt[i],1)   A=Σ 1/len, B=Σ u1[src]/len
//   d2u[i] = (du[i]*A[i] - C[i]) / max(cnt[i],1)   C=Σ du[src]/len
//   loss   = ((u0-u1)/dt + du*u1 - MU*d2u) * mask
//
// V = Σ (256 + 1/len) = 256*cnt + A packs cnt+A into one float ->
// pass 1 is a single red.global.add.v2.f32 {V,B} per edge (8B RMW).
//
// ZERO-INVARIANT: __device__ globals are zero-initialized at module load;
// k_final restores g_acc/g_C to zero after consuming them, so accumulators
// are all-zero at every kernel_launch entry (k_init deleted).
//
// This round: k_final processes 8 nodes/thread with front-batched loads
// (MLP ~12 128b loads in flight) — it was at DRAM=66%/issue=13%, limited by
// per-thread memory-level parallelism, not bytes.

#define N_NODES 4000000
#define N_EDGES 8000000
#define INV_DT  100.0f
#define MU      0.01f
#define K_PACK  256.0f
#define INV_K   0.00390625f   // 1/256

__device__ float2 g_acc[N_NODES];   // {V = 256*cnt + A, B}  (zero at entry)
__device__ float  g_C[N_NODES];     // Σ du[src]/len          (zero at entry)
__device__ float  g_du[N_NODES];    // written by k_du, gathered by k_edge2

// unpack V and compute du (fast reciprocal)
__device__ __forceinline__ float node_du(float V, float B, float u1,
                                         float& A, float& rc) {
    float k = floorf(V * INV_K);          // cnt
    A  = V - K_PACK * k;
    rc = __fdividef(1.0f, fmaxf(k, 1.0f));
    return (u1 * A - B) * rc;
}

// ---------------------------------------------------------------------------
// pass 1 (4 edges/thread): gather x_t1[2s]; red.v2 {V += 256+1/len, B += u1[s]/len}
__global__ void __launch_bounds__(256) k_edge1(const int4* __restrict__ ei_s,
                                               const int4* __restrict__ ei_d,
                                               const float4* __restrict__ attr,
                                               const float* __restrict__ x_t1) {
    int t = blockIdx.x * blockDim.x + threadIdx.x;
    if (t >= N_EDGES / 4) return;
    int4   s4 = __ldcs(&ei_s[t]);
    int4   d4 = __ldcs(&ei_d[t]);
    float4 l4 = __ldcs(&attr[t]);

    float u0 = __ldg(&x_t1[2 * s4.x]);
    float u1 = __ldg(&x_t1[2 * s4.y]);
    float u2 = __ldg(&x_t1[2 * s4.z]);
    float u3 = __ldg(&x_t1[2 * s4.w]);

    float r0 = __fdividef(1.0f, l4.x);
    float r1 = __fdividef(1.0f, l4.y);
    float r2 = __fdividef(1.0f, l4.z);
    float r3 = __fdividef(1.0f, l4.w);

    asm volatile("red.global.add.v2.f32 [%0], {%1, %2};"
                 :: "l"(&g_acc[d4.x]), "f"(K_PACK + r0), "f"(u0 * r0) : "memory");
    asm volatile("red.global.add.v2.f32 [%0], {%1, %2};"
                 :: "l"(&g_acc[d4.y]), "f"(K_PACK + r1), "f"(u1 * r1) : "memory");
    asm volatile("red.global.add.v2.f32 [%0], {%1, %2};"
                 :: "l"(&g_acc[d4.z]), "f"(K_PACK + r2), "f"(u2 * r2) : "memory");
    asm volatile("red.global.add.v2.f32 [%0], {%1, %2};"
                 :: "l"(&g_acc[d4.w]), "f"(K_PACK + r3), "f"(u3 * r3) : "memory");
}

// node pass (4 nodes/thread): du = (u1*A - B) / max(cnt,1)
__global__ void __launch_bounds__(256) k_du(const float4* __restrict__ x_t1) {
    int t = blockIdx.x * blockDim.x + threadIdx.x;
    if (t >= N_NODES / 4) return;
    float4 xa = __ldg(&x_t1[t * 2 + 0]);   // u1[4t],v,u1[4t+1],v
    float4 xb = __ldg(&x_t1[t * 2 + 1]);   // u1[4t+2],v,u1[4t+3],v
    float4 p0 = ((const float4*)g_acc)[t * 2 + 0];  // {V0,B0,V1,B1}
    float4 p1 = ((const float4*)g_acc)[t * 2 + 1];  // {V2,B2,V3,B3}
    float A, rc;
    float4 du;
    du.x = node_du(p0.x, p0.y, xa.x, A, rc);
    du.y = node_du(p0.z, p0.w, xa.z, A, rc);
    du.z = node_du(p1.x, p1.y, xb.x, A, rc);
    du.w = node_du(p1.z, p1.w, xb.z, A, rc);
    ((float4*)g_du)[t] = du;
}

// pass 2 (4 edges/thread): C[d] += du[s]/len
__global__ void __launch_bounds__(256) k_edge2(const int4* __restrict__ ei_s,
                                               const int4* __restrict__ ei_d,
                                               const float4* __restrict__ attr) {
    int t = blockIdx.x * blockDim.x + threadIdx.x;
    if (t >= N_EDGES / 4) return;
    int4   s4 = __ldcs(&ei_s[t]);
    int4   d4 = __ldcs(&ei_d[t]);
    float4 l4 = __ldcs(&attr[t]);

    float d0 = __ldg(&g_du[s4.x]);
    float d1 = __ldg(&g_du[s4.y]);
    float d2 = __ldg(&g_du[s4.z]);
    float d3 = __ldg(&g_du[s4.w]);

    atomicAdd(&g_C[d4.x], d0 * __fdividef(1.0f, l4.x));
    atomicAdd(&g_C[d4.y], d1 * __fdividef(1.0f, l4.y));
    atomicAdd(&g_C[d4.z], d2 * __fdividef(1.0f, l4.z));
    atomicAdd(&g_C[d4.w], d3 * __fdividef(1.0f, l4.w));
}

// epilogue (8 nodes/thread, front-batched loads): loss + zero-restore
__device__ __forceinline__ float node_loss(float V, float B, float C,
                                           float u0, float u1, float m) {
    float A, rc;
    float du  = node_du(V, B, u1, A, rc);
    float d2u = (du * A - C) * rc;
    return ((u0 - u1) * INV_DT + du * u1 - MU * d2u) * m;
}

__global__ void __launch_bounds__(256) k_final(const float4* __restrict__ x_t,
                                               const float4* __restrict__ x_t1,
                                               const float4* __restrict__ mask,
                                               float4* __restrict__ out) {
    int t = blockIdx.x * blockDim.x + threadIdx.x;
    if (t >= N_NODES / 8) return;

    // front-batch all loads (12x128b in flight)
    float4 p0 = __ldcs(&((const float4*)g_acc)[t * 4 + 0]);  // {V,B} n0,n1
    float4 p1 = __ldcs(&((const float4*)g_acc)[t * 4 + 1]);  // {V,B} n2,n3
    float4 p2 = __ldcs(&((const float4*)g_acc)[t * 4 + 2]);  // {V,B} n4,n5
    float4 p3 = __ldcs(&((const float4*)g_acc)[t * 4 + 3]);  // {V,B} n6,n7
    float4 C0 = __ldcs(&((const float4*)g_C)[t * 2 + 0]);
    float4 C1 = __ldcs(&((const float4*)g_C)[t * 2 + 1]);
    float4 y0 = __ldg(&x_t1[t * 4 + 0]);
    float4 y1 = __ldg(&x_t1[t * 4 + 1]);
    float4 y2 = __ldg(&x_t1[t * 4 + 2]);
    float4 y3 = __ldg(&x_t1[t * 4 + 3]);
    float4 x0 = __ldcs(&x_t[t * 4 + 0]);
    float4 x1 = __ldcs(&x_t[t * 4 + 1]);
    float4 x2 = __ldcs(&x_t[t * 4 + 2]);
    float4 x3 = __ldcs(&x_t[t * 4 + 3]);
    float4 m0 = __ldcs(&mask[t * 2 + 0]);
    float4 m1 = __ldcs(&mask[t * 2 + 1]);

    float4 oa, ob;
    oa.x = node_loss(p0.x, p0.y, C0.x, x0.x, y0.x, m0.x);
    oa.y = node_loss(p0.z, p0.w, C0.y, x0.z, y0.z, m0.y);
    oa.z = node_loss(p1.x, p1.y, C0.z, x1.x, y1.x, m0.z);
    oa.w = node_loss(p1.z, p1.w, C0.w, x1.z, y1.z, m0.w);
    ob.x = node_loss(p2.x, p2.y, C1.x, x2.x, y2.x, m1.x);
    ob.y = node_loss(p2.z, p2.w, C1.y, x2.z, y2.z, m1.y);
    ob.z = node_loss(p3.x, p3.y, C1.z, x3.x, y3.x, m1.z);
    ob.w = node_loss(p3.z, p3.w, C1.w, x3.z, y3.z, m1.w);
    __stcs(&out[t * 2 + 0], oa);
    __stcs(&out[t * 2 + 1], ob);

    // restore the zero-invariant for the next launch
    float4 z = make_float4(0.f, 0.f, 0.f, 0.f);
    ((float4*)g_acc)[t * 4 + 0] = z;
    ((float4*)g_acc)[t * 4 + 1] = z;
    ((float4*)g_acc)[t * 4 + 2] = z;
    ((float4*)g_acc)[t * 4 + 3] = z;
    ((float4*)g_C)[t * 2 + 0] = z;
    ((float4*)g_C)[t * 2 + 1] = z;
}

// ---------------------------------------------------------------------------
extern "C" void kernel_launch(void* const* d_in, const int* in_sizes, int n_in,
                              void* d_out, int out_size) {
    const float4* x_t   = (const float4*)d_in[0];
    const float*  x_t1  = (const float*)d_in[1];
    const float4* x_t1v = (const float4*)d_in[1];
    const int*    ei    = (const int*)d_in[2];
    const float4* attr  = (const float4*)d_in[3];
    const float4* mask  = (const float4*)d_in[4];
    float4*       out   = (float4*)d_out;

    const int4* ei_s = (const int4*)ei;
    const int4* ei_d = (const int4*)(ei + N_EDGES);

    const int TB = 256;
    const int gn  = (N_NODES / 4 + TB - 1) / TB;
    const int gn8 = (N_NODES / 8 + TB - 1) / TB;
    const int ge  = (N_EDGES / 4 + TB - 1) / TB;

    k_edge1<<<ge,  TB>>>(ei_s, ei_d, attr, x_t1);
    k_du   <<<gn,  TB>>>(x_t1v);
    k_edge2<<<ge,  TB>>>(ei_s, ei_d, attr);
    k_final<<<gn8, TB>>>(x_t, x_t1v, mask, out);
}